// round 6
// baseline (speedup 1.0000x reference)
#include <cuda_runtime.h>
#include <cstdint>

#define Bsz 512
#define Tt  256
#define Hh  256
#define Pp  14

// grid: 128 CTAs = 8 batch groups (64 batches) x 16 hidden slices (16 h each)
#define NGROUPS 8

// ---------------- global scratch (no allocations allowed) ----------------
__device__ float g_h1[2][Bsz * Hh];      // layer-0 hidden, double buffered
__device__ float g_h2[2][Bsz * Hh];      // layer-1 hidden, double buffered
__device__ float g_xT[Tt * Bsz];         // x transposed to [T][B]
__device__ unsigned g_arrive[NGROUPS];
__device__ unsigned g_release[NGROUPS];

// ---------------- smem layout (floats) ----------------
// wp0   : 16384   layer0 w_hh slice, fragment-packed
// wp1h  : 16384   layer1 w_hh slice
// wp1x  : 16384   layer1 w_ih slice
// abuf  : 64*68   A staging / gate buffer (union)
// bias0, wih0c, bias1, xsm : 64 each
#define SMEM_FLOATS (16384 * 3 + 64 * 68 + 4 * 64)
#define SMEM_BYTES  (SMEM_FLOATS * 4)

// ---------------- helpers ----------------
__device__ __forceinline__ unsigned f2tf(float x) {
    unsigned u; asm("cvt.rna.tf32.f32 %0, %1;" : "=r"(u) : "f"(x)); return u;
}
__device__ __forceinline__ float sigm(float x) {
    return __fdividef(1.0f, 1.0f + __expf(-x));
}
__device__ __forceinline__ float tanh_(float x) {
    float ax = fabsf(x);
    float e  = __expf(-2.0f * ax);
    float r  = __fdividef(1.0f - e, 1.0f + e);
    return copysignf(r, x);
}
__device__ __forceinline__ void mma8(float d[4], const unsigned a[4],
                                     unsigned b0, unsigned b1) {
    asm volatile(
        "mma.sync.aligned.m16n8k8.row.col.f32.tf32.tf32.f32 "
        "{%0,%1,%2,%3}, {%4,%5,%6,%7}, {%8,%9}, {%0,%1,%2,%3};"
        : "+f"(d[0]), "+f"(d[1]), "+f"(d[2]), "+f"(d[3])
        : "r"(a[0]), "r"(a[1]), "r"(a[2]), "r"(a[3]), "r"(b0), "r"(b1));
}

// Pack a 64-gate-row x 256-k weight slice into B-fragment order (tf32 RNA).
// dst[((kt*8 + nt)*32 + lane)*2 + j] = W[nt*8 + lane/4][kt*8 + lane%4 + 4j]
__device__ void pack_weights(float* dst, const float* __restrict__ W, int hs) {
    for (int idx = threadIdx.x; idx < 16384; idx += 128) {
        int j    = idx & 1;
        int lane = (idx >> 1) & 31;
        int nt   = (idx >> 6) & 7;
        int kt   = idx >> 9;
        int n    = nt * 8 + (lane >> 2);
        int k    = kt * 8 + (lane & 3) + j * 4;
        int gt   = n >> 4, hloc = n & 15;
        int grow = gt * 256 + hs * 16 + hloc;     // PyTorch gate order i,f,g,o
        dst[idx] = __uint_as_float(f2tf(W[grow * 256 + k]));
    }
}

// One K=256 GEMM: acc[64x64] += h_tile[64x256] @ Wslice^T, staged in 4 chunks.
__device__ __forceinline__ void gemm_k256(
    float acc[2][4][4],
    const float* __restrict__ src,     // global: this CTA's 64 batch rows [row*256 + k]
    const float* __restrict__ wpack,
    float* __restrict__ abuf,
    int wm, int wn, int lane)
{
    const int tid = threadIdx.x;
    for (int kc = 0; kc < 4; kc++) {
        // stage chunk (L2-only loads: other SMs wrote this data -> bypass stale L1)
        #pragma unroll
        for (int i = 0; i < 8; i++) {
            int v = tid + i * 128;
            int flat = v * 4;
            int row = flat >> 6;
            int kk  = flat & 63;
            float4 val = __ldcg((const float4*)(src + row * 256 + kc * 64 + kk));
            float4 o;
            o.x = __uint_as_float(f2tf(val.x));
            o.y = __uint_as_float(f2tf(val.y));
            o.z = __uint_as_float(f2tf(val.z));
            o.w = __uint_as_float(f2tf(val.w));
            *(float4*)(abuf + row * 68 + kk) = o;
        }
        __syncthreads();
        #pragma unroll
        for (int ks = 0; ks < 8; ks++) {
            int ktile = kc * 8 + ks;
            int k0 = ks * 8;
            unsigned a[2][4];
            #pragma unroll
            for (int mt = 0; mt < 2; mt++) {
                int r = wm + mt * 16 + (lane >> 2);
                int c = k0 + (lane & 3);
                a[mt][0] = __float_as_uint(abuf[r * 68 + c]);
                a[mt][1] = __float_as_uint(abuf[(r + 8) * 68 + c]);
                a[mt][2] = __float_as_uint(abuf[r * 68 + c + 4]);
                a[mt][3] = __float_as_uint(abuf[(r + 8) * 68 + c + 4]);
            }
            #pragma unroll
            for (int nt = 0; nt < 4; nt++) {
                int ntile = (wn >> 3) + nt;
                float2 bb = *(const float2*)(wpack + ((ktile * 8 + ntile) * 32 + lane) * 2);
                unsigned b0 = __float_as_uint(bb.x);
                unsigned b1 = __float_as_uint(bb.y);
                mma8(acc[0][nt], a[0], b0, b1);
                mma8(acc[1][nt], a[1], b0, b1);
            }
        }
        __syncthreads();
    }
}

__device__ __forceinline__ void store_gates(float acc[2][4][4], float* abuf,
                                            int wm, int wn, int lane) {
    #pragma unroll
    for (int mt = 0; mt < 2; mt++)
        #pragma unroll
        for (int nt = 0; nt < 4; nt++) {
            int r  = wm + mt * 16 + (lane >> 2);
            int cc = wn + nt * 8 + (lane & 3) * 2;
            abuf[r * 68 + cc]           = acc[mt][nt][0];
            abuf[r * 68 + cc + 1]       = acc[mt][nt][1];
            abuf[(r + 8) * 68 + cc]     = acc[mt][nt][2];
            abuf[(r + 8) * 68 + cc + 1] = acc[mt][nt][3];
        }
}

// Per-batch-group barrier: 16 CTAs, monotonic arrive counter + release generation.
__device__ __forceinline__ void group_barrier(int grp, unsigned target) {
    __threadfence();          // all threads: publish my stores at GPU scope
    __syncthreads();
    if (threadIdx.x == 0) {
        unsigned prev = atomicAdd(&g_arrive[grp], 1u);
        if (prev == target * 16u - 1u) {
            atomicExch(&g_release[grp], target);
        } else {
            volatile unsigned* rel = &g_release[grp];
            while (*rel < target) __nanosleep(64);
        }
        __threadfence();
    }
    __syncthreads();
}

// ---------------- kernels ----------------
__global__ void reset_kernel(const float* __restrict__ x) {
    int idx = blockIdx.x * blockDim.x + threadIdx.x;   // 512 * 256 = 131072
    g_h1[0][idx] = 0.0f;
    g_h2[0][idx] = 0.0f;
    int t = idx >> 9, b = idx & 511;
    g_xT[idx] = x[b * Tt + t];                          // x is [B][T][1]
    if (idx < NGROUPS) { g_arrive[idx] = 0u; g_release[idx] = 0u; }
}

__global__ void __launch_bounds__(128, 1)
lstm_main(const float* __restrict__ w_ih0, const float* __restrict__ w_hh0,
          const float* __restrict__ b_ih0, const float* __restrict__ b_hh0,
          const float* __restrict__ w_ih1, const float* __restrict__ w_hh1,
          const float* __restrict__ b_ih1, const float* __restrict__ b_hh1)
{
    extern __shared__ float smem[];
    float* wp0   = smem;
    float* wp1h  = smem + 16384;
    float* wp1x  = smem + 32768;
    float* abuf  = smem + 49152;           // 64*68 = 4352
    float* bias0 = smem + 49152 + 4352;
    float* wih0c = bias0 + 64;
    float* bias1 = wih0c + 64;
    float* xsm   = bias1 + 64;

    const int tid  = threadIdx.x;
    const int lane = tid & 31;
    const int warp = tid >> 5;
    const int wm   = (warp >> 1) * 32;
    const int wn   = (warp & 1) * 32;
    const int bg   = blockIdx.x >> 4;      // batch group 0..7
    const int hs   = blockIdx.x & 15;      // hidden slice 0..15
    const int brow0 = bg * 64;

    pack_weights(wp0,  w_hh0, hs);
    pack_weights(wp1h, w_hh1, hs);
    pack_weights(wp1x, w_ih1, hs);
    if (tid < 64) {
        int n = tid, gt = n >> 4, hloc = n & 15;
        int grow = gt * 256 + hs * 16 + hloc;
        bias0[n] = b_ih0[grow] + b_hh0[grow];
        wih0c[n] = w_ih0[grow];             // w_ih0 is [1024][1]
        bias1[n] = b_ih1[grow] + b_hh1[grow];
    }
    __syncthreads();

    float c0s[8], c1s[8];
    #pragma unroll
    for (int j = 0; j < 8; j++) { c0s[j] = 0.0f; c1s[j] = 0.0f; }

    for (int t = 0; t < Tt; t++) {
        // ================= phase A: layer 0 =================
        if (tid < 64) xsm[tid] = g_xT[t * Bsz + brow0 + tid];
        float acc[2][4][4];
        #pragma unroll
        for (int mt = 0; mt < 2; mt++)
            #pragma unroll
            for (int nt = 0; nt < 4; nt++)
                #pragma unroll
                for (int q = 0; q < 4; q++) acc[mt][nt][q] = 0.0f;

        gemm_k256(acc, &g_h1[t & 1][brow0 * Hh], wp0, abuf, wm, wn, lane);
        store_gates(acc, abuf, wm, wn, lane);
        __syncthreads();

        #pragma unroll
        for (int j = 0; j < 8; j++) {
            int cell = tid + j * 128;
            int b = cell >> 4, h = cell & 15;
            float xv = xsm[b];
            float gi = abuf[b * 68 + h]      + xv * wih0c[h]      + bias0[h];
            float gf = abuf[b * 68 + 16 + h] + xv * wih0c[16 + h] + bias0[16 + h];
            float gg = abuf[b * 68 + 32 + h] + xv * wih0c[32 + h] + bias0[32 + h];
            float go = abuf[b * 68 + 48 + h] + xv * wih0c[48 + h] + bias0[48 + h];
            float iv = sigm(gi), fv = sigm(gf), gv = tanh_(gg), ov = sigm(go);
            c0s[j] = fv * c0s[j] + iv * gv;
            g_h1[(t + 1) & 1][(brow0 + b) * Hh + hs * 16 + h] = ov * tanh_(c0s[j]);
        }

        group_barrier(bg, (unsigned)(t + 1));   // one barrier per step suffices

        // ================= phase B: layer 1 (K = 512 fused) =================
        #pragma unroll
        for (int mt = 0; mt < 2; mt++)
            #pragma unroll
            for (int nt = 0; nt < 4; nt++)
                #pragma unroll
                for (int q = 0; q < 4; q++) acc[mt][nt][q] = 0.0f;

        gemm_k256(acc, &g_h2[t & 1][brow0 * Hh],       wp1h, abuf, wm, wn, lane);
        gemm_k256(acc, &g_h1[(t + 1) & 1][brow0 * Hh], wp1x, abuf, wm, wn, lane);
        store_gates(acc, abuf, wm, wn, lane);
        __syncthreads();

        #pragma unroll
        for (int j = 0; j < 8; j++) {
            int cell = tid + j * 128;
            int b = cell >> 4, h = cell & 15;
            float gi = abuf[b * 68 + h]      + bias1[h];
            float gf = abuf[b * 68 + 16 + h] + bias1[16 + h];
            float gg = abuf[b * 68 + 32 + h] + bias1[32 + h];
            float go = abuf[b * 68 + 48 + h] + bias1[48 + h];
            float iv = sigm(gi), fv = sigm(gf), gv = tanh_(gg), ov = sigm(go);
            c1s[j] = fv * c1s[j] + iv * gv;
            g_h2[(t + 1) & 1][(brow0 + b) * Hh + hs * 16 + h] = ov * tanh_(c1s[j]);
        }
        __syncthreads();   // abuf / xsm reuse safety before next step's staging
    }
}

__global__ void epilogue_kernel(const float* __restrict__ w_lin,
                                const float* __restrict__ b_lin,
                                float* __restrict__ out) {
    int b = blockIdx.x;
    int lane = threadIdx.x;            // 32 threads
    float hv[8];
    #pragma unroll
    for (int j = 0; j < 8; j++)
        hv[j] = g_h2[0][b * Hh + lane + j * 32];   // final buffer: (255+1)&1 = 0
    for (int p = 0; p < Pp; p++) {
        float s = 0.0f;
        #pragma unroll
        for (int j = 0; j < 8; j++)
            s += hv[j] * w_lin[p * Hh + lane + j * 32];
        #pragma unroll
        for (int off = 16; off > 0; off >>= 1)
            s += __shfl_xor_sync(0xFFFFFFFFu, s, off);
        if (lane == 0) out[b * Pp + p] = s + b_lin[p];
    }
}

// ---------------- launch ----------------
extern "C" void kernel_launch(void* const* d_in, const int* in_sizes, int n_in,
                              void* d_out, int out_size) {
    const float* x     = (const float*)d_in[0];
    const float* w_ih0 = (const float*)d_in[1];
    const float* w_hh0 = (const float*)d_in[2];
    const float* b_ih0 = (const float*)d_in[3];
    const float* b_hh0 = (const float*)d_in[4];
    const float* w_ih1 = (const float*)d_in[5];
    const float* w_hh1 = (const float*)d_in[6];
    const float* b_ih1 = (const float*)d_in[7];
    const float* b_hh1 = (const float*)d_in[8];
    const float* w_lin = (const float*)d_in[9];
    const float* b_lin = (const float*)d_in[10];

    cudaFuncSetAttribute(lstm_main, cudaFuncAttributeMaxDynamicSharedMemorySize,
                         SMEM_BYTES);

    reset_kernel<<<512, 256>>>(x);
    lstm_main<<<128, 128, SMEM_BYTES>>>(w_ih0, w_hh0, b_ih0, b_hh0,
                                        w_ih1, w_hh1, b_ih1, b_hh1);
    epilogue_kernel<<<Bsz, 32>>>(w_lin, b_lin, (float*)d_out);
}

// round 7
// speedup vs baseline: 1.5065x; 1.5065x over previous
#include <cuda_runtime.h>
#include <cuda_fp16.h>
#include <cstdint>

#define Bsz 512
#define Tt  256
#define Hh  256
#define Pp  14
#define NGROUPS 8

// ---------------- global scratch ----------------
__device__ __half g_h1[2][Bsz * Hh];     // layer-0 hidden (fp16), double buffered
__device__ __half g_h2[2][Bsz * Hh];     // layer-1 hidden (fp16), double buffered
__device__ float  g_xT[Tt * Bsz];        // x transposed to [T][B]
__device__ unsigned g_arrive[NGROUPS];
__device__ unsigned g_release[NGROUPS];

// ---------------- smem layout (byte offsets) ----------------
// wp0/wp1h/wp1x: fragment-packed fp16 weight slices, 32KB each
// stg0/stg1: h staging, 64 rows x 72 halves (144B stride, ldmatrix conflict-free)
// abuf: fp32 gate buffer 64x68
#define OFF_WP0   0
#define OFF_WP1H  32768
#define OFF_WP1X  65536
#define OFF_STG0  98304
#define OFF_STG1  107520
#define OFF_ABUF  116736
#define OFF_BIAS0 134144
#define OFF_WIH0  134400
#define OFF_BIAS1 134656
#define OFF_XSM   134912
#define SMEM_BYTES 135168

// ---------------- helpers ----------------
__device__ __forceinline__ float sigm(float x) {
    return __fdividef(1.0f, 1.0f + __expf(-x));
}
__device__ __forceinline__ float tanh_(float x) {
    float ax = fabsf(x);
    float e  = __expf(-2.0f * ax);
    float r  = __fdividef(1.0f - e, 1.0f + e);
    return copysignf(r, x);
}
__device__ __forceinline__ unsigned sptr(const void* p) {
    return (unsigned)__cvta_generic_to_shared(p);
}
__device__ __forceinline__ void cpasync16(unsigned saddr, const void* g) {
    asm volatile("cp.async.cg.shared.global [%0], [%1], 16;" :: "r"(saddr), "l"(g));
}
#define CP_COMMIT() asm volatile("cp.async.commit_group;")
#define CP_WAIT1()  asm volatile("cp.async.wait_group 1;")
#define CP_WAIT0()  asm volatile("cp.async.wait_group 0;")

__device__ __forceinline__ void mma16816(float d[4], const unsigned a[4],
                                         unsigned b0, unsigned b1) {
    asm volatile(
        "mma.sync.aligned.m16n8k16.row.col.f32.f16.f16.f32 "
        "{%0,%1,%2,%3}, {%4,%5,%6,%7}, {%8,%9}, {%0,%1,%2,%3};"
        : "+f"(d[0]), "+f"(d[1]), "+f"(d[2]), "+f"(d[3])
        : "r"(a[0]), "r"(a[1]), "r"(a[2]), "r"(a[3]), "r"(b0), "r"(b1));
}

// Pack 64-gate x 256-k fp32 weight slice into fp16 B-fragment order.
// Layout: u32 dst[((kk*4 + npair)*32 + lane)*4 + q]
//   ntile = npair*2 + (q>>1), reg = q&1
//   value = half2( W[n][k0], W[n][k0+1] ), n = ntile*8 + lane/4,
//   k0 = kk*16 + (lane%4)*2 + reg*8     (mma m16n8k16 B fragment layout)
__device__ void pack_weights(unsigned* dst, const float* __restrict__ W, int hs) {
    for (int idx = threadIdx.x; idx < 8192; idx += 256) {
        int q = idx & 3, lane = (idx >> 2) & 31, npair = (idx >> 7) & 3, kk = idx >> 9;
        int ntile = npair * 2 + (q >> 1), reg = q & 1;
        int n  = ntile * 8 + (lane >> 2);
        int k0 = kk * 16 + (lane & 3) * 2 + reg * 8;
        int grow = (n >> 4) * 256 + hs * 16 + (n & 15);   // gate order i,f,g,o
        __half2 v = __floats2half2_rn(W[grow * 256 + k0], W[grow * 256 + k0 + 1]);
        dst[idx] = *reinterpret_cast<unsigned*>(&v);
    }
}

// Stage one K=64 chunk of a 64-row fp16 tile: global [row*256 + kc*64 ..] ->
// smem [row*72 ..] via cp.async.cg (L2-only: coherent with other SMs' stores).
__device__ __forceinline__ void stage_chunk(__half* dst, const __half* __restrict__ src,
                                            int kc, int tid) {
    unsigned base = sptr(dst);
    #pragma unroll
    for (int i = 0; i < 2; i++) {
        int seg = tid + i * 256;          // 512 x 16B
        int row = seg >> 3, s = seg & 7;
        cpasync16(base + (unsigned)((row * 72 + s * 8) * 2),
                  src + row * 256 + kc * 64 + s * 8);
    }
}

// One K=64 chunk of MMA: acc[32x32 per warp] += A_chunk @ Wslice^T
__device__ __forceinline__ void compute_chunk(float acc[2][4][4], const __half* sb,
                                              const uint4* __restrict__ wp, int kc,
                                              int wm, int wn, int lane) {
    unsigned sbase = sptr(sb);
    #pragma unroll
    for (int ks = 0; ks < 4; ks++) {
        unsigned a[2][4];
        int colbase = ks * 16 + (lane >> 4) * 8;
        #pragma unroll
        for (int mt = 0; mt < 2; mt++) {
            int row = wm + mt * 16 + (lane & 7) + ((lane >> 3) & 1) * 8;
            unsigned ad = sbase + (unsigned)((row * 72 + colbase) * 2);
            asm volatile("ldmatrix.sync.aligned.m8n8.x4.shared.b16 {%0,%1,%2,%3}, [%4];"
                : "=r"(a[mt][0]), "=r"(a[mt][1]), "=r"(a[mt][2]), "=r"(a[mt][3])
                : "r"(ad));
        }
        int kkg = kc * 4 + ks;
        uint4 b01 = wp[(kkg * 4 + (wn >> 4)) * 32 + lane];
        uint4 b23 = wp[(kkg * 4 + (wn >> 4) + 1) * 32 + lane];
        #pragma unroll
        for (int mt = 0; mt < 2; mt++) {
            mma16816(acc[mt][0], a[mt], b01.x, b01.y);
            mma16816(acc[mt][1], a[mt], b01.z, b01.w);
            mma16816(acc[mt][2], a[mt], b23.x, b23.y);
            mma16816(acc[mt][3], a[mt], b23.z, b23.w);
        }
    }
}

__device__ __forceinline__ void store_gates(float acc[2][4][4], float* abuf,
                                            int wm, int wn, int lane) {
    #pragma unroll
    for (int mt = 0; mt < 2; mt++)
        #pragma unroll
        for (int nt = 0; nt < 4; nt++) {
            int r  = wm + mt * 16 + (lane >> 2);
            int cc = wn + nt * 8 + (lane & 3) * 2;
            abuf[r * 68 + cc]           = acc[mt][nt][0];
            abuf[r * 68 + cc + 1]       = acc[mt][nt][1];
            abuf[(r + 8) * 68 + cc]     = acc[mt][nt][2];
            abuf[(r + 8) * 68 + cc + 1] = acc[mt][nt][3];
        }
}

// Per-batch-group barrier: 16 CTAs (identical to R5's proven implementation).
__device__ __forceinline__ void group_barrier(int grp, unsigned target) {
    __threadfence();
    __syncthreads();
    if (threadIdx.x == 0) {
        unsigned prev = atomicAdd(&g_arrive[grp], 1u);
        if (prev == target * 16u - 1u) {
            atomicExch(&g_release[grp], target);
        } else {
            volatile unsigned* rel = &g_release[grp];
            while (*rel < target) __nanosleep(32);
        }
        __threadfence();
    }
    __syncthreads();
}

// ---------------- kernels ----------------
__global__ void reset_kernel(const float* __restrict__ x) {
    int idx = blockIdx.x * blockDim.x + threadIdx.x;   // 131072
    g_h1[0][idx] = __float2half(0.0f);
    g_h2[0][idx] = __float2half(0.0f);
    int t = idx >> 9, b = idx & 511;
    g_xT[idx] = x[b * Tt + t];
    if (idx < NGROUPS) { g_arrive[idx] = 0u; g_release[idx] = 0u; }
}

__global__ void __launch_bounds__(256, 1)
lstm_main(const float* __restrict__ w_ih0, const float* __restrict__ w_hh0,
          const float* __restrict__ b_ih0, const float* __restrict__ b_hh0,
          const float* __restrict__ w_ih1, const float* __restrict__ w_hh1,
          const float* __restrict__ b_ih1, const float* __restrict__ b_hh1)
{
    extern __shared__ char smem[];
    const uint4* wp0  = (const uint4*)(smem + OFF_WP0);
    const uint4* wp1h = (const uint4*)(smem + OFF_WP1H);
    const uint4* wp1x = (const uint4*)(smem + OFF_WP1X);
    __half* stg[2] = { (__half*)(smem + OFF_STG0), (__half*)(smem + OFF_STG1) };
    float* abuf  = (float*)(smem + OFF_ABUF);
    float* bias0 = (float*)(smem + OFF_BIAS0);
    float* wih0c = (float*)(smem + OFF_WIH0);
    float* bias1 = (float*)(smem + OFF_BIAS1);
    float* xsm   = (float*)(smem + OFF_XSM);

    const int tid  = threadIdx.x;
    const int lane = tid & 31;
    const int warp = tid >> 5;
    const int wm   = (warp & 1) * 32;          // valid for warps 0-3
    const int wn   = ((warp >> 1) & 1) * 32;
    const int bg   = blockIdx.x >> 4;
    const int hs   = blockIdx.x & 15;
    const int brow0 = bg * 64;

    pack_weights((unsigned*)(smem + OFF_WP0),  w_hh0, hs);
    pack_weights((unsigned*)(smem + OFF_WP1H), w_hh1, hs);
    pack_weights((unsigned*)(smem + OFF_WP1X), w_ih1, hs);
    if (tid < 64) {
        int n = tid, gt = n >> 4, hloc = n & 15;
        int grow = gt * 256 + hs * 16 + hloc;
        bias0[n] = b_ih0[grow] + b_hh0[grow];
        wih0c[n] = w_ih0[grow];
        bias1[n] = b_ih1[grow] + b_hh1[grow];
    }
    __syncthreads();

    float c0s[4] = {0, 0, 0, 0}, c1s[4] = {0, 0, 0, 0};

    // prefetch phase-A chunk0 for t=0 (zeros buffer, valid data)
    stage_chunk(stg[0], &g_h1[0][brow0 * Hh], 0, tid);
    CP_COMMIT();

    for (int t = 0; t < Tt; t++) {
        const __half* h1old = &g_h1[t & 1][brow0 * Hh];
        __half*       h1new = &g_h1[(t + 1) & 1][brow0 * Hh];
        const __half* h2old = &g_h2[t & 1][brow0 * Hh];
        __half*       h2new = &g_h2[(t + 1) & 1][brow0 * Hh];

        if (tid < 64) xsm[tid] = g_xT[t * Bsz + brow0 + tid];

        float acc[2][4][4];
        #pragma unroll
        for (int mt = 0; mt < 2; mt++)
            #pragma unroll
            for (int nt = 0; nt < 4; nt++)
                #pragma unroll
                for (int q = 0; q < 4; q++) acc[mt][nt][q] = 0.0f;

        // ============ phase A: layer 0, K=256 (4 chunks, pipelined) ============
        #pragma unroll 1
        for (int kc = 0; kc < 4; kc++) {
            if (kc < 3) stage_chunk(stg[(kc + 1) & 1], h1old, kc + 1, tid);
            CP_COMMIT();
            if (kc < 3) { CP_WAIT1(); } else { CP_WAIT0(); }
            __syncthreads();
            if (warp < 4) compute_chunk(acc, stg[kc & 1], wp0, kc, wm, wn, lane);
            __syncthreads();
        }
        if (warp < 4) store_gates(acc, abuf, wm, wn, lane);
        __syncthreads();

        #pragma unroll
        for (int j = 0; j < 4; j++) {
            int cell = tid + j * 256;
            int b = cell >> 4, h = cell & 15;
            float xv = xsm[b];
            float gi = abuf[b * 68 + h]      + xv * wih0c[h]      + bias0[h];
            float gf = abuf[b * 68 + 16 + h] + xv * wih0c[16 + h] + bias0[16 + h];
            float gg = abuf[b * 68 + 32 + h] + xv * wih0c[32 + h] + bias0[32 + h];
            float go = abuf[b * 68 + 48 + h] + xv * wih0c[48 + h] + bias0[48 + h];
            float iv = sigm(gi), fv = sigm(gf), gv = tanh_(gg), ov = sigm(go);
            c0s[j] = fv * c0s[j] + iv * gv;
            h1new[b * Hh + hs * 16 + h] = __float2half(ov * tanh_(c0s[j]));
        }

        group_barrier(bg, (unsigned)(t + 1));

        // ============ phase B: layer 1, K=512 fused (8 chunks, pipelined) ============
        #pragma unroll
        for (int mt = 0; mt < 2; mt++)
            #pragma unroll
            for (int nt = 0; nt < 4; nt++)
                #pragma unroll
                for (int q = 0; q < 4; q++) acc[mt][nt][q] = 0.0f;

        stage_chunk(stg[0], h2old, 0, tid);
        CP_COMMIT();
        #pragma unroll 1
        for (int c = 0; c < 8; c++) {
            if (c < 7) {
                const __half* s = (c + 1 < 4) ? h2old : (const __half*)h1new;
                stage_chunk(stg[(c + 1) & 1], s, (c + 1) & 3, tid);
            } else if (t + 1 < Tt) {
                // hoist: next step's phase-A chunk0 (h1[t+1] is final after barrier)
                stage_chunk(stg[0], h1new, 0, tid);
            }
            CP_COMMIT();
            CP_WAIT1();
            __syncthreads();
            if (warp < 4)
                compute_chunk(acc, stg[c & 1], (c < 4) ? wp1h : wp1x, c & 3, wm, wn, lane);
            __syncthreads();
        }
        if (warp < 4) store_gates(acc, abuf, wm, wn, lane);
        __syncthreads();

        #pragma unroll
        for (int j = 0; j < 4; j++) {
            int cell = tid + j * 256;
            int b = cell >> 4, h = cell & 15;
            float gi = abuf[b * 68 + h]      + bias1[h];
            float gf = abuf[b * 68 + 16 + h] + bias1[16 + h];
            float gg = abuf[b * 68 + 32 + h] + bias1[32 + h];
            float go = abuf[b * 68 + 48 + h] + bias1[48 + h];
            float iv = sigm(gi), fv = sigm(gf), gv = tanh_(gg), ov = sigm(go);
            c1s[j] = fv * c1s[j] + iv * gv;
            h2new[b * Hh + hs * 16 + h] = __float2half(ov * tanh_(c1s[j]));
        }
        __syncthreads();
    }
}

__global__ void epilogue_kernel(const float* __restrict__ w_lin,
                                const float* __restrict__ b_lin,
                                float* __restrict__ out) {
    int b = blockIdx.x;
    int lane = threadIdx.x;            // 32 threads
    float hv[8];
    #pragma unroll
    for (int j = 0; j < 8; j++)
        hv[j] = __half2float(g_h2[0][b * Hh + lane + j * 32]);   // (255+1)&1 = 0
    for (int p = 0; p < Pp; p++) {
        float s = 0.0f;
        #pragma unroll
        for (int j = 0; j < 8; j++)
            s += hv[j] * w_lin[p * Hh + lane + j * 32];
        #pragma unroll
        for (int off = 16; off > 0; off >>= 1)
            s += __shfl_xor_sync(0xFFFFFFFFu, s, off);
        if (lane == 0) out[b * Pp + p] = s + b_lin[p];
    }
}

// ---------------- launch ----------------
extern "C" void kernel_launch(void* const* d_in, const int* in_sizes, int n_in,
                              void* d_out, int out_size) {
    const float* x     = (const float*)d_in[0];
    const float* w_ih0 = (const float*)d_in[1];
    const float* w_hh0 = (const float*)d_in[2];
    const float* b_ih0 = (const float*)d_in[3];
    const float* b_hh0 = (const float*)d_in[4];
    const float* w_ih1 = (const float*)d_in[5];
    const float* w_hh1 = (const float*)d_in[6];
    const float* b_ih1 = (const float*)d_in[7];
    const float* b_hh1 = (const float*)d_in[8];
    const float* w_lin = (const float*)d_in[9];
    const float* b_lin = (const float*)d_in[10];

    cudaFuncSetAttribute(lstm_main, cudaFuncAttributeMaxDynamicSharedMemorySize,
                         SMEM_BYTES);

    reset_kernel<<<512, 256>>>(x);
    lstm_main<<<128, 256, SMEM_BYTES>>>(w_ih0, w_hh0, b_ih0, b_hh0,
                                        w_ih1, w_hh1, b_ih1, b_hh1);
    epilogue_kernel<<<Bsz, 32>>>(w_lin, b_lin, (float*)d_out);
}

// round 8
// speedup vs baseline: 1.7851x; 1.1850x over previous
#include <cuda_runtime.h>
#include <cuda_fp16.h>
#include <cstdint>

#define Bsz 512
#define Tt  256
#define Hh  256
#define Pp  14
#define NGROUPS 8
#define STRD 264   // staging row stride in halves (528B: ldmatrix conflict-free)

// ---------------- global scratch ----------------
__device__ __half g_h1[2][Bsz * Hh];
__device__ __half g_h2[2][Bsz * Hh];
__device__ float  g_xT[Tt * Bsz];
__device__ unsigned g_arrive[NGROUPS];
__device__ unsigned g_release[NGROUPS];

// ---------------- smem layout (byte offsets) ----------------
#define OFF_WP0   0
#define OFF_WP1H  32768
#define OFF_WP1X  65536
#define OFF_H1A   98304
#define OFF_H1B   132096
#define OFF_H2    165888
#define OFF_ABUF  199680
#define OFF_BIAS0 217088
#define OFF_WIH0  217344
#define OFF_BIAS1 217600
#define OFF_XSM   217856
#define SMEM_BYTES 218112

// ---------------- helpers ----------------
__device__ __forceinline__ float tanh_a(float x) {
    float r; asm("tanh.approx.f32 %0, %1;" : "=f"(r) : "f"(x)); return r;
}
__device__ __forceinline__ float sigm(float x) {
    return fmaf(tanh_a(0.5f * x), 0.5f, 0.5f);
}
__device__ __forceinline__ unsigned sptr(const void* p) {
    return (unsigned)__cvta_generic_to_shared(p);
}
__device__ __forceinline__ void cpasync16(unsigned saddr, const void* g) {
    asm volatile("cp.async.cg.shared.global [%0], [%1], 16;" :: "r"(saddr), "l"(g));
}
#define CP_COMMIT() asm volatile("cp.async.commit_group;")
#define CP_WAIT(n)  asm volatile("cp.async.wait_group %0;" :: "n"(n))

__device__ __forceinline__ void mma16816(float d[4], const unsigned a[4],
                                         unsigned b0, unsigned b1) {
    asm volatile(
        "mma.sync.aligned.m16n8k16.row.col.f32.f16.f16.f32 "
        "{%0,%1,%2,%3}, {%4,%5,%6,%7}, {%8,%9}, {%0,%1,%2,%3};"
        : "+f"(d[0]), "+f"(d[1]), "+f"(d[2]), "+f"(d[3])
        : "r"(a[0]), "r"(a[1]), "r"(a[2]), "r"(a[3]), "r"(b0), "r"(b1));
}

// Pack 64-gate x 256-k fp32 weight slice into fp16 B-fragment order (as R6).
__device__ void pack_weights(unsigned* dst, const float* __restrict__ W, int hs) {
    for (int idx = threadIdx.x; idx < 8192; idx += 256) {
        int q = idx & 3, lane = (idx >> 2) & 31, npair = (idx >> 7) & 3, kk = idx >> 9;
        int ntile = npair * 2 + (q >> 1), reg = q & 1;
        int n  = ntile * 8 + (lane >> 2);
        int k0 = kk * 16 + (lane & 3) * 2 + reg * 8;
        int grow = (n >> 4) * 256 + hs * 16 + (n & 15);   // gate order i,f,g,o
        __half2 v = __floats2half2_rn(W[grow * 256 + k0], W[grow * 256 + k0 + 1]);
        dst[idx] = *reinterpret_cast<unsigned*>(&v);
    }
}

// Stage one 128-col half of a 64-row fp16 tile via cp.async.cg (L2-coherent).
__device__ __forceinline__ void stage_half(void* dst, const __half* __restrict__ src,
                                           int colhalf, int tid) {
    unsigned base = sptr(dst);
    #pragma unroll
    for (int i = 0; i < 4; i++) {
        int seg = tid + i * 256;               // 1024 x 16B
        int row = seg >> 4, s = seg & 15;
        int col = colhalf * 128 + s * 8;
        cpasync16(base + (unsigned)((row * STRD + col) * 2),
                  src + row * 256 + col);
    }
}

// nsteps K=16 MMA steps starting at kbase: acc[32x16 per warp] += A @ W^T
__device__ __forceinline__ void gemm_ksteps(float acc[2][2][4], const __half* tile,
                                            const uint4* __restrict__ wp,
                                            int kbase, int nsteps,
                                            int wm, int npair, int lane) {
    unsigned sbase = sptr(tile);
    #pragma unroll 4
    for (int k = 0; k < nsteps; k++) {
        int kk = kbase + k;
        unsigned a[2][4];
        int colb = kk * 16 + (lane >> 4) * 8;
        #pragma unroll
        for (int mt = 0; mt < 2; mt++) {
            int row = wm + mt * 16 + (lane & 7) + ((lane >> 3) & 1) * 8;
            unsigned ad = sbase + (unsigned)((row * STRD + colb) * 2);
            asm volatile("ldmatrix.sync.aligned.m8n8.x4.shared.b16 {%0,%1,%2,%3}, [%4];"
                : "=r"(a[mt][0]), "=r"(a[mt][1]), "=r"(a[mt][2]), "=r"(a[mt][3])
                : "r"(ad));
        }
        uint4 b = wp[(kk * 4 + npair) * 32 + lane];
        #pragma unroll
        for (int mt = 0; mt < 2; mt++) {
            mma16816(acc[mt][0], a[mt], b.x, b.y);
            mma16816(acc[mt][1], a[mt], b.z, b.w);
        }
    }
}

__device__ __forceinline__ void store_gates(float acc[2][2][4], float* abuf,
                                            int wm, int wn, int lane) {
    #pragma unroll
    for (int mt = 0; mt < 2; mt++)
        #pragma unroll
        for (int nt = 0; nt < 2; nt++) {
            int r  = wm + mt * 16 + (lane >> 2);
            int cc = wn + nt * 8 + (lane & 3) * 2;
            abuf[r * 68 + cc]           = acc[mt][nt][0];
            abuf[r * 68 + cc + 1]       = acc[mt][nt][1];
            abuf[(r + 8) * 68 + cc]     = acc[mt][nt][2];
            abuf[(r + 8) * 68 + cc + 1] = acc[mt][nt][3];
        }
}

// Per-batch-group barrier: 16 CTAs (proven in R5/R6).
__device__ __forceinline__ void group_barrier(int grp, unsigned target) {
    __threadfence();
    __syncthreads();
    if (threadIdx.x == 0) {
        unsigned prev = atomicAdd(&g_arrive[grp], 1u);
        if (prev == target * 16u - 1u) {
            atomicExch(&g_release[grp], target);
        } else {
            volatile unsigned* rel = &g_release[grp];
            while (*rel < target) __nanosleep(32);
        }
        __threadfence();
    }
    __syncthreads();
}

// ---------------- kernels ----------------
__global__ void reset_kernel(const float* __restrict__ x) {
    int idx = blockIdx.x * blockDim.x + threadIdx.x;   // 131072
    g_h1[0][idx] = __float2half(0.0f);
    g_h2[0][idx] = __float2half(0.0f);
    int t = idx >> 9, b = idx & 511;
    g_xT[idx] = x[b * Tt + t];
    if (idx < NGROUPS) { g_arrive[idx] = 0u; g_release[idx] = 0u; }
}

__global__ void __launch_bounds__(256, 1)
lstm_main(const float* __restrict__ w_ih0, const float* __restrict__ w_hh0,
          const float* __restrict__ b_ih0, const float* __restrict__ b_hh0,
          const float* __restrict__ w_ih1, const float* __restrict__ w_hh1,
          const float* __restrict__ b_ih1, const float* __restrict__ b_hh1)
{
    extern __shared__ char smem[];
    const uint4* wp0  = (const uint4*)(smem + OFF_WP0);
    const uint4* wp1h = (const uint4*)(smem + OFF_WP1H);
    const uint4* wp1x = (const uint4*)(smem + OFF_WP1X);
    __half* stgH1[2] = { (__half*)(smem + OFF_H1A), (__half*)(smem + OFF_H1B) };
    __half* stgH2 = (__half*)(smem + OFF_H2);
    float* abuf  = (float*)(smem + OFF_ABUF);
    float* bias0 = (float*)(smem + OFF_BIAS0);
    float* wih0c = (float*)(smem + OFF_WIH0);
    float* bias1 = (float*)(smem + OFF_BIAS1);
    float* xsm   = (float*)(smem + OFF_XSM);

    const int tid   = threadIdx.x;
    const int lane  = tid & 31;
    const int warp  = tid >> 5;
    const int wm    = (warp & 1) * 32;      // 2 x 4 warp grid over 64x64
    const int npair = warp >> 1;            // 16-col group
    const int wn    = npair * 16;
    const int bg    = blockIdx.x >> 4;
    const int hs    = blockIdx.x & 15;
    const int brow0 = bg * 64;

    pack_weights((unsigned*)(smem + OFF_WP0),  w_hh0, hs);
    pack_weights((unsigned*)(smem + OFF_WP1H), w_hh1, hs);
    pack_weights((unsigned*)(smem + OFF_WP1X), w_ih1, hs);
    if (tid < 64) {
        int n = tid, gt = n >> 4, hloc = n & 15;
        int grow = gt * 256 + hs * 16 + hloc;
        bias0[n] = b_ih0[grow] + b_hh0[grow];
        wih0c[n] = w_ih0[grow];
        bias1[n] = b_ih1[grow] + b_hh1[grow];
    }

    float c0s[4] = {0, 0, 0, 0}, c1s[4] = {0, 0, 0, 0};

    // prologue: stage h1[0] (zeros) for phase A of t=0
    stage_half(stgH1[0], &g_h1[0][brow0 * Hh], 0, tid);
    stage_half(stgH1[0], &g_h1[0][brow0 * Hh], 1, tid);
    CP_COMMIT();
    CP_WAIT(0);
    __syncthreads();

    for (int t = 0; t < Tt; t++) {
        const __half* h2old = &g_h2[t & 1][brow0 * Hh];
        __half*       h1new = &g_h1[(t + 1) & 1][brow0 * Hh];
        __half*       h2new = &g_h2[(t + 1) & 1][brow0 * Hh];

        if (tid < 64) xsm[tid] = g_xT[t * Bsz + brow0 + tid];

        // ============ phase A: layer 0, K=256 from resident stgH1[t&1] ============
        float acc[2][2][4];
        #pragma unroll
        for (int mt = 0; mt < 2; mt++)
            #pragma unroll
            for (int nt = 0; nt < 2; nt++)
                #pragma unroll
                for (int q = 0; q < 4; q++) acc[mt][nt][q] = 0.0f;

        gemm_ksteps(acc, stgH1[t & 1], wp0, 0, 16, wm, npair, lane);
        store_gates(acc, abuf, wm, wn, lane);
        __syncthreads();

        #pragma unroll
        for (int j = 0; j < 4; j++) {
            int cell = tid + j * 256;
            int b = cell >> 4, h = cell & 15;
            float xv = xsm[b];
            float gi = abuf[b * 68 + h]      + xv * wih0c[h]      + bias0[h];
            float gf = abuf[b * 68 + 16 + h] + xv * wih0c[16 + h] + bias0[16 + h];
            float gg = abuf[b * 68 + 32 + h] + xv * wih0c[32 + h] + bias0[32 + h];
            float go = abuf[b * 68 + 48 + h] + xv * wih0c[48 + h] + bias0[48 + h];
            float iv = sigm(gi), fv = sigm(gf), gv = tanh_a(gg), ov = sigm(go);
            c0s[j] = fv * c0s[j] + iv * gv;
            h1new[b * Hh + hs * 16 + h] = __float2half(ov * tanh_a(c0s[j]));
        }

        group_barrier(bg, (unsigned)(t + 1));

        // ============ stage h2old (2 groups) + h1new (1 group, reused by t+1) ======
        stage_half(stgH2, h2old, 0, tid); CP_COMMIT();
        stage_half(stgH2, h2old, 1, tid); CP_COMMIT();
        stage_half(stgH1[(t + 1) & 1], h1new, 0, tid);
        stage_half(stgH1[(t + 1) & 1], h1new, 1, tid);
        CP_COMMIT();

        // ============ phase B: layer 1, K=512 = [h2old | h1new] ============
        #pragma unroll
        for (int mt = 0; mt < 2; mt++)
            #pragma unroll
            for (int nt = 0; nt < 2; nt++)
                #pragma unroll
                for (int q = 0; q < 4; q++) acc[mt][nt][q] = 0.0f;

        CP_WAIT(2);
        __syncthreads();
        gemm_ksteps(acc, stgH2, wp1h, 0, 8, wm, npair, lane);
        CP_WAIT(1);
        __syncthreads();
        gemm_ksteps(acc, stgH2, wp1h, 8, 8, wm, npair, lane);
        CP_WAIT(0);
        __syncthreads();
        gemm_ksteps(acc, stgH1[(t + 1) & 1], wp1x, 0, 16, wm, npair, lane);
        store_gates(acc, abuf, wm, wn, lane);
        __syncthreads();

        #pragma unroll
        for (int j = 0; j < 4; j++) {
            int cell = tid + j * 256;
            int b = cell >> 4, h = cell & 15;
            float gi = abuf[b * 68 + h]      + bias1[h];
            float gf = abuf[b * 68 + 16 + h] + bias1[16 + h];
            float gg = abuf[b * 68 + 32 + h] + bias1[32 + h];
            float go = abuf[b * 68 + 48 + h] + bias1[48 + h];
            float iv = sigm(gi), fv = sigm(gf), gv = tanh_a(gg), ov = sigm(go);
            c1s[j] = fv * c1s[j] + iv * gv;
            h2new[b * Hh + hs * 16 + h] = __float2half(ov * tanh_a(c1s[j]));
        }
        __syncthreads();
    }
}

__global__ void epilogue_kernel(const float* __restrict__ w_lin,
                                const float* __restrict__ b_lin,
                                float* __restrict__ out) {
    int b = blockIdx.x;
    int lane = threadIdx.x;            // 32 threads
    float hv[8];
    #pragma unroll
    for (int j = 0; j < 8; j++)
        hv[j] = __half2float(g_h2[0][b * Hh + lane + j * 32]);   // (255+1)&1 = 0
    for (int p = 0; p < Pp; p++) {
        float s = 0.0f;
        #pragma unroll
        for (int j = 0; j < 8; j++)
            s += hv[j] * w_lin[p * Hh + lane + j * 32];
        #pragma unroll
        for (int off = 16; off > 0; off >>= 1)
            s += __shfl_xor_sync(0xFFFFFFFFu, s, off);
        if (lane == 0) out[b * Pp + p] = s + b_lin[p];
    }
}

// ---------------- launch ----------------
extern "C" void kernel_launch(void* const* d_in, const int* in_sizes, int n_in,
                              void* d_out, int out_size) {
    const float* x     = (const float*)d_in[0];
    const float* w_ih0 = (const float*)d_in[1];
    const float* w_hh0 = (const float*)d_in[2];
    const float* b_ih0 = (const float*)d_in[3];
    const float* b_hh0 = (const float*)d_in[4];
    const float* w_ih1 = (const float*)d_in[5];
    const float* w_hh1 = (const float*)d_in[6];
    const float* b_ih1 = (const float*)d_in[7];
    const float* b_hh1 = (const float*)d_in[8];
    const float* w_lin = (const float*)d_in[9];
    const float* b_lin = (const float*)d_in[10];

    cudaFuncSetAttribute(lstm_main, cudaFuncAttributeMaxDynamicSharedMemorySize,
                         SMEM_BYTES);

    reset_kernel<<<512, 256>>>(x);
    lstm_main<<<128, 256, SMEM_BYTES>>>(w_ih0, w_hh0, b_ih0, b_hh0,
                                        w_ih1, w_hh1, b_ih1, b_hh1);
    epilogue_kernel<<<Bsz, 32>>>(w_lin, b_lin, (float*)d_out);
}

// round 11
// speedup vs baseline: 1.8698x; 1.0475x over previous
#include <cuda_runtime.h>
#include <cuda_fp16.h>
#include <cstdint>

#define Bsz 512
#define Tt  256
#define Hh  256
#define Pp  14
#define NGROUPS 8
#define STRD 264   // staging row stride in halves (528B: ldmatrix conflict-free)

// ---------------- global scratch ----------------
__device__ __half g_h1[2][Bsz * Hh];
__device__ __half g_h2[2][Bsz * Hh];
__device__ float  g_xT[Tt * Bsz];
__device__ unsigned g_arrive[NGROUPS];
__device__ unsigned g_release[NGROUPS];

// ---------------- smem layout (byte offsets) ----------------
#define OFF_WP0   0
#define OFF_WP1H  32768
#define OFF_WP1X  65536
#define OFF_H1A   98304
#define OFF_H1B   132096
#define OFF_H2    165888
#define OFF_ABUF  199680
#define OFF_BIAS0 217088
#define OFF_WIH0  217344
#define OFF_BIAS1 217600
#define OFF_XSM   217856
#define SMEM_BYTES 218112

// ---------------- helpers ----------------
__device__ __forceinline__ float tanh_a(float x) {
    float r; asm("tanh.approx.f32 %0, %1;" : "=f"(r) : "f"(x)); return r;
}
__device__ __forceinline__ float sigm(float x) {
    return fmaf(tanh_a(0.5f * x), 0.5f, 0.5f);
}
__device__ __forceinline__ unsigned sptr(const void* p) {
    return (unsigned)__cvta_generic_to_shared(p);
}
__device__ __forceinline__ void cpasync16(unsigned saddr, const void* g) {
    asm volatile("cp.async.cg.shared.global [%0], [%1], 16;" :: "r"(saddr), "l"(g));
}
#define CP_COMMIT() asm volatile("cp.async.commit_group;")
#define CP_WAIT(n)  asm volatile("cp.async.wait_group %0;" :: "n"(n))

__device__ __forceinline__ void mma16816(float d[4], const unsigned a[4],
                                         unsigned b0, unsigned b1) {
    asm volatile(
        "mma.sync.aligned.m16n8k16.row.col.f32.f16.f16.f32 "
        "{%0,%1,%2,%3}, {%4,%5,%6,%7}, {%8,%9}, {%0,%1,%2,%3};"
        : "+f"(d[0]), "+f"(d[1]), "+f"(d[2]), "+f"(d[3])
        : "r"(a[0]), "r"(a[1]), "r"(a[2]), "r"(a[3]), "r"(b0), "r"(b1));
}

// Pack 64-gate x 256-k fp32 weight slice into fp16 B-fragment order (as R6/R7).
__device__ void pack_weights(unsigned* dst, const float* __restrict__ W, int hs) {
    for (int idx = threadIdx.x; idx < 8192; idx += 256) {
        int q = idx & 3, lane = (idx >> 2) & 31, npair = (idx >> 7) & 3, kk = idx >> 9;
        int ntile = npair * 2 + (q >> 1), reg = q & 1;
        int n  = ntile * 8 + (lane >> 2);
        int k0 = kk * 16 + (lane & 3) * 2 + reg * 8;
        int grow = (n >> 4) * 256 + hs * 16 + (n & 15);   // gate order i,f,g,o
        __half2 v = __floats2half2_rn(W[grow * 256 + k0], W[grow * 256 + k0 + 1]);
        dst[idx] = *reinterpret_cast<unsigned*>(&v);
    }
}

// Stage one 128-col half of a 64-row fp16 tile via cp.async.cg (L2-coherent).
__device__ __forceinline__ void stage_half(void* dst, const __half* __restrict__ src,
                                           int colhalf, int tid) {
    unsigned base = sptr(dst);
    #pragma unroll
    for (int i = 0; i < 4; i++) {
        int seg = tid + i * 256;               // 1024 x 16B
        int row = seg >> 4, s = seg & 15;
        int col = colhalf * 128 + s * 8;
        cpasync16(base + (unsigned)((row * STRD + col) * 2),
                  src + row * 256 + col);
    }
}

// nsteps K=16 MMA steps: acc[32x32 per warp] += A @ W^T  (warps 0-3, 2x2 grid)
__device__ __forceinline__ void gemm_ksteps(float acc[2][4][4], const __half* tile,
                                            const uint4* __restrict__ wp,
                                            int kbase, int nsteps,
                                            int wm, int wn, int lane) {
    unsigned sbase = sptr(tile);
    #pragma unroll 4
    for (int k = 0; k < nsteps; k++) {
        int kk = kbase + k;
        unsigned a[2][4];
        int colb = kk * 16 + (lane >> 4) * 8;
        #pragma unroll
        for (int mt = 0; mt < 2; mt++) {
            int row = wm + mt * 16 + (lane & 7) + ((lane >> 3) & 1) * 8;
            unsigned ad = sbase + (unsigned)((row * STRD + colb) * 2);
            asm volatile("ldmatrix.sync.aligned.m8n8.x4.shared.b16 {%0,%1,%2,%3}, [%4];"
                : "=r"(a[mt][0]), "=r"(a[mt][1]), "=r"(a[mt][2]), "=r"(a[mt][3])
                : "r"(ad));
        }
        uint4 b01 = wp[(kk * 4 + (wn >> 4)) * 32 + lane];
        uint4 b23 = wp[(kk * 4 + (wn >> 4) + 1) * 32 + lane];
        #pragma unroll
        for (int mt = 0; mt < 2; mt++) {
            mma16816(acc[mt][0], a[mt], b01.x, b01.y);
            mma16816(acc[mt][1], a[mt], b01.z, b01.w);
            mma16816(acc[mt][2], a[mt], b23.x, b23.y);
            mma16816(acc[mt][3], a[mt], b23.z, b23.w);
        }
    }
}

__device__ __forceinline__ void store_gates(float acc[2][4][4], float* abuf,
                                            int wm, int wn, int lane) {
    #pragma unroll
    for (int mt = 0; mt < 2; mt++)
        #pragma unroll
        for (int nt = 0; nt < 4; nt++) {
            int r  = wm + mt * 16 + (lane >> 2);
            int cc = wn + nt * 8 + (lane & 3) * 2;
            abuf[r * 68 + cc]           = acc[mt][nt][0];
            abuf[r * 68 + cc + 1]       = acc[mt][nt][1];
            abuf[(r + 8) * 68 + cc]     = acc[mt][nt][2];
            abuf[(r + 8) * 68 + cc + 1] = acc[mt][nt][3];
        }
}

// Per-batch-group barrier: 16 CTAs (proven R5-R8).
__device__ __forceinline__ void group_barrier(int grp, unsigned target) {
    __threadfence();
    __syncthreads();
    if (threadIdx.x == 0) {
        unsigned prev = atomicAdd(&g_arrive[grp], 1u);
        if (prev == target * 16u - 1u) {
            atomicExch(&g_release[grp], target);
        } else {
            volatile unsigned* rel = &g_release[grp];
            while (*rel < target) __nanosleep(32);
        }
        __threadfence();
    }
    __syncthreads();
}

// ---------------- kernels ----------------
__global__ void reset_kernel(const float* __restrict__ x) {
    int idx = blockIdx.x * blockDim.x + threadIdx.x;   // 131072
    g_h1[0][idx] = __float2half(0.0f);
    g_h2[0][idx] = __float2half(0.0f);
    int t = idx >> 9, b = idx & 511;
    g_xT[idx] = x[b * Tt + t];
    if (idx < NGROUPS) { g_arrive[idx] = 0u; g_release[idx] = 0u; }
}

__global__ void __launch_bounds__(256, 1)
lstm_main(const float* __restrict__ w_ih0, const float* __restrict__ w_hh0,
          const float* __restrict__ b_ih0, const float* __restrict__ b_hh0,
          const float* __restrict__ w_ih1, const float* __restrict__ w_hh1,
          const float* __restrict__ b_ih1, const float* __restrict__ b_hh1)
{
    extern __shared__ char smem[];
    const uint4* wp0  = (const uint4*)(smem + OFF_WP0);
    const uint4* wp1h = (const uint4*)(smem + OFF_WP1H);
    const uint4* wp1x = (const uint4*)(smem + OFF_WP1X);
    __half* stgH1[2] = { (__half*)(smem + OFF_H1A), (__half*)(smem + OFF_H1B) };
    __half* stgH2 = (__half*)(smem + OFF_H2);
    float* abuf  = (float*)(smem + OFF_ABUF);
    float* bias0 = (float*)(smem + OFF_BIAS0);
    float* wih0c = (float*)(smem + OFF_WIH0);
    float* bias1 = (float*)(smem + OFF_BIAS1);
    float* xsm   = (float*)(smem + OFF_XSM);

    const int tid  = threadIdx.x;
    const int lane = tid & 31;
    const int warp = tid >> 5;
    const int wm   = (warp & 1) * 32;          // warps 0-3: 2x2 grid of 32x32
    const int wn   = ((warp >> 1) & 1) * 32;
    const int bg   = blockIdx.x >> 4;
    const int hs   = blockIdx.x & 15;
    const int brow0 = bg * 64;

    pack_weights((unsigned*)(smem + OFF_WP0),  w_hh0, hs);
    pack_weights((unsigned*)(smem + OFF_WP1H), w_hh1, hs);
    pack_weights((unsigned*)(smem + OFF_WP1X), w_ih1, hs);
    if (tid < 64) {
        int n = tid, gt = n >> 4, hloc = n & 15;
        int grow = gt * 256 + hs * 16 + hloc;
        bias0[n] = b_ih0[grow] + b_hh0[grow];
        wih0c[n] = w_ih0[grow];
        bias1[n] = b_ih1[grow] + b_hh1[grow];
    }

    float c0s[4] = {0, 0, 0, 0}, c1s[4] = {0, 0, 0, 0};

    // prologue: stage h1[0] (zeros) for phase A of t=0
    stage_half(stgH1[0], &g_h1[0][brow0 * Hh], 0, tid);
    stage_half(stgH1[0], &g_h1[0][brow0 * Hh], 1, tid);
    CP_COMMIT();
    CP_WAIT(0);
    __syncthreads();

    for (int t = 0; t < Tt; t++) {
        const __half* h2old = &g_h2[t & 1][brow0 * Hh];
        __half*       h1new = &g_h1[(t + 1) & 1][brow0 * Hh];
        __half*       h2new = &g_h2[(t + 1) & 1][brow0 * Hh];

        if (tid < 64) xsm[tid] = g_xT[t * Bsz + brow0 + tid];

        // ============ phase A: layer 0, K=256 from resident stgH1[t&1] ============
        float acc[2][4][4];
        if (warp < 4) {
            #pragma unroll
            for (int mt = 0; mt < 2; mt++)
                #pragma unroll
                for (int nt = 0; nt < 4; nt++)
                    #pragma unroll
                    for (int q = 0; q < 4; q++) acc[mt][nt][q] = 0.0f;
            gemm_ksteps(acc, stgH1[t & 1], wp0, 0, 16, wm, wn, lane);
            store_gates(acc, abuf, wm, wn, lane);
        }
        __syncthreads();

        #pragma unroll
        for (int j = 0; j < 4; j++) {
            int cell = tid + j * 256;
            int b = cell >> 4, h = cell & 15;
            float xv = xsm[b];
            float gi = abuf[b * 68 + h]      + xv * wih0c[h]      + bias0[h];
            float gf = abuf[b * 68 + 16 + h] + xv * wih0c[16 + h] + bias0[16 + h];
            float gg = abuf[b * 68 + 32 + h] + xv * wih0c[32 + h] + bias0[32 + h];
            float go = abuf[b * 68 + 48 + h] + xv * wih0c[48 + h] + bias0[48 + h];
            float iv = sigm(gi), fv = sigm(gf), gv = tanh_a(gg), ov = sigm(go);
            c0s[j] = fv * c0s[j] + iv * gv;
            h1new[b * Hh + hs * 16 + h] = __float2half(ov * tanh_a(c0s[j]));
        }

        group_barrier(bg, (unsigned)(t + 1));

        // ===== stage h2old (2 groups) + h1new (1 group, reused by t+1) =====
        stage_half(stgH2, h2old, 0, tid); CP_COMMIT();
        stage_half(stgH2, h2old, 1, tid); CP_COMMIT();
        stage_half(stgH1[(t + 1) & 1], h1new, 0, tid);
        stage_half(stgH1[(t + 1) & 1], h1new, 1, tid);
        CP_COMMIT();

        // ============ phase B: layer 1, K=512 = [h2old | h1new] ============
        if (warp < 4) {
            #pragma unroll
            for (int mt = 0; mt < 2; mt++)
                #pragma unroll
                for (int nt = 0; nt < 4; nt++)
                    #pragma unroll
                    for (int q = 0; q < 4; q++) acc[mt][nt][q] = 0.0f;
        }

        CP_WAIT(2);
        __syncthreads();
        if (warp < 4) gemm_ksteps(acc, stgH2, wp1h, 0, 8, wm, wn, lane);
        CP_WAIT(1);
        __syncthreads();
        if (warp < 4) gemm_ksteps(acc, stgH2, wp1h, 8, 8, wm, wn, lane);
        CP_WAIT(0);
        __syncthreads();
        if (warp < 4) {
            gemm_ksteps(acc, stgH1[(t + 1) & 1], wp1x, 0, 16, wm, wn, lane);
            store_gates(acc, abuf, wm, wn, lane);
        }
        __syncthreads();

        #pragma unroll
        for (int j = 0; j < 4; j++) {
            int cell = tid + j * 256;
            int b = cell >> 4, h = cell & 15;
            float gi = abuf[b * 68 + h]      + bias1[h];
            float gf = abuf[b * 68 + 16 + h] + bias1[16 + h];
            float gg = abuf[b * 68 + 32 + h] + bias1[32 + h];
            float go = abuf[b * 68 + 48 + h] + bias1[48 + h];
            float iv = sigm(gi), fv = sigm(gf), gv = tanh_a(gg), ov = sigm(go);
            c1s[j] = fv * c1s[j] + iv * gv;
            h2new[b * Hh + hs * 16 + h] = __float2half(ov * tanh_a(c1s[j]));
        }
        __syncthreads();
    }
}

__global__ void epilogue_kernel(const float* __restrict__ w_lin,
                                const float* __restrict__ b_lin,
                                float* __restrict__ out) {
    int b = blockIdx.x;
    int lane = threadIdx.x;            // 32 threads
    float hv[8];
    #pragma unroll
    for (int j = 0; j < 8; j++)
        hv[j] = __half2float(g_h2[0][b * Hh + lane + j * 32]);   // (255+1)&1 = 0
    for (int p = 0; p < Pp; p++) {
        float s = 0.0f;
        #pragma unroll
        for (int j = 0; j < 8; j++)
            s += hv[j] * w_lin[p * Hh + lane + j * 32];
        #pragma unroll
        for (int off = 16; off > 0; off >>= 1)
            s += __shfl_xor_sync(0xFFFFFFFFu, s, off);
        if (lane == 0) out[b * Pp + p] = s + b_lin[p];
    }
}

// ---------------- launch ----------------
extern "C" void kernel_launch(void* const* d_in, const int* in_sizes, int n_in,
                              void* d_out, int out_size) {
    const float* x     = (const float*)d_in[0];
    const float* w_ih0 = (const float*)d_in[1];
    const float* w_hh0 = (const float*)d_in[2];
    const float* b_ih0 = (const float*)d_in[3];
    const float* b_hh0 = (const float*)d_in[4];
    const float* w_ih1 = (const float*)d_in[5];
    const float* w_hh1 = (const float*)d_in[6];
    const float* b_ih1 = (const float*)d_in[7];
    const float* b_hh1 = (const float*)d_in[8];
    const float* w_lin = (const float*)d_in[9];
    const float* b_lin = (const float*)d_in[10];

    cudaFuncSetAttribute(lstm_main, cudaFuncAttributeMaxDynamicSharedMemorySize,
                         SMEM_BYTES);

    reset_kernel<<<512, 256>>>(x);
    lstm_main<<<128, 256, SMEM_BYTES>>>(w_ih0, w_hh0, b_ih0, b_hh0,
                                        w_ih1, w_hh1, b_ih1, b_hh1);
    epilogue_kernel<<<Bsz, 32>>>(w_lin, b_lin, (float*)d_out);
}

// round 12
// speedup vs baseline: 2.3819x; 1.2738x over previous
#include <cuda_runtime.h>
#include <cuda_fp16.h>
#include <cstdint>

#define Bsz 512
#define Tt  256
#define Hh  256
#define Pp  14
#define NGROUPS 8
#define GSIZE   16
#define STRD 264   // staging row stride in halves (528B: ldmatrix conflict-free)

// ---------------- global scratch ----------------
__device__ __half g_h1[2][Bsz * Hh];
__device__ __half g_h2[2][Bsz * Hh];
__device__ float  g_xT[Tt * Bsz];
__device__ unsigned g_f1[128];   // per-CTA step flag: h1(t+1) published
__device__ unsigned g_f2[128];   // per-CTA step flag: h2(t+1) published

// ---------------- smem layout (byte offsets) ----------------
#define OFF_WP0   0         // 32KB  w_hh0 packed (WG0)
#define OFF_WP1H  32768     // 32KB  w_hh1 packed (WG1)
#define OFF_WP1X  65536     // 32KB  w_ih1 packed (WG1)
#define OFF_H1A   98304     // 33792 h1 tile 64x256 @ stride 264 (WG0 stages, both read)
#define OFF_H2    132096    // 33792 h2 tile (WG1)
#define OFF_ABUFA 165888    // 17408 fp32 gates 64x68 (WG0)
#define OFF_ABUFB 183296    // 17408 (WG1)
#define OFF_BIAS0 200704
#define OFF_WIH0  200960
#define OFF_BIAS1 201216
#define SMEM_BYTES 201472

// ---------------- helpers ----------------
__device__ __forceinline__ float tanh_a(float x) {
    float r; asm("tanh.approx.f32 %0, %1;" : "=f"(r) : "f"(x)); return r;
}
__device__ __forceinline__ float sigm(float x) {
    return fmaf(tanh_a(0.5f * x), 0.5f, 0.5f);
}
__device__ __forceinline__ unsigned sptr(const void* p) {
    return (unsigned)__cvta_generic_to_shared(p);
}
__device__ __forceinline__ void cpasync16(unsigned saddr, const void* g) {
    asm volatile("cp.async.cg.shared.global [%0], [%1], 16;" :: "r"(saddr), "l"(g));
}
#define CP_COMMIT() asm volatile("cp.async.commit_group;")
#define CP_WAIT0()  asm volatile("cp.async.wait_group 0;")
#define BAR_SYNC(id, n)   asm volatile("bar.sync %0, %1;"   :: "r"(id), "n"(n) : "memory")
#define BAR_ARRIVE(id, n) asm volatile("bar.arrive %0, %1;" :: "r"(id), "n"(n) : "memory")

__device__ __forceinline__ void mma16816(float d[4], const unsigned a[4],
                                         unsigned b0, unsigned b1) {
    asm volatile(
        "mma.sync.aligned.m16n8k16.row.col.f32.f16.f16.f32 "
        "{%0,%1,%2,%3}, {%4,%5,%6,%7}, {%8,%9}, {%0,%1,%2,%3};"
        : "+f"(d[0]), "+f"(d[1]), "+f"(d[2]), "+f"(d[3])
        : "r"(a[0]), "r"(a[1]), "r"(a[2]), "r"(a[3]), "r"(b0), "r"(b1));
}

// Pack 64-gate x 256-k fp32 weight slice into fp16 B-fragment order (proven R6-R11).
__device__ void pack_weights(unsigned* dst, const float* __restrict__ W, int hs) {
    for (int idx = threadIdx.x; idx < 8192; idx += 256) {
        int q = idx & 3, lane = (idx >> 2) & 31, npair = (idx >> 7) & 3, kk = idx >> 9;
        int ntile = npair * 2 + (q >> 1), reg = q & 1;
        int n  = ntile * 8 + (lane >> 2);
        int k0 = kk * 16 + (lane & 3) * 2 + reg * 8;
        int grow = (n >> 4) * 256 + hs * 16 + (n & 15);   // gate order i,f,g,o
        __half2 v = __floats2half2_rn(W[grow * 256 + k0], W[grow * 256 + k0 + 1]);
        dst[idx] = *reinterpret_cast<unsigned*>(&v);
    }
}

// Stage a full 64x256 fp16 tile (32KB) with 128 threads via cp.async.cg (L2-coherent).
__device__ __forceinline__ void stage_tile128(void* dst, const __half* __restrict__ src,
                                              int wg_tid) {
    unsigned base = sptr(dst);
    #pragma unroll
    for (int i = 0; i < 16; i++) {
        int seg = wg_tid + i * 128;            // 2048 x 16B
        int row = seg >> 5, s = seg & 31;
        cpasync16(base + (unsigned)((row * STRD + s * 8) * 2),
                  src + row * 256 + s * 8);
    }
}

// nsteps K=16 MMA steps: acc[32x32 per warp] += A @ W^T  (4 warps, 2x2 grid; proven R11)
__device__ __forceinline__ void gemm_ksteps(float acc[2][4][4], const __half* tile,
                                            const uint4* __restrict__ wp,
                                            int kbase, int nsteps,
                                            int wm, int wn, int lane) {
    unsigned sbase = sptr(tile);
    #pragma unroll 4
    for (int k = 0; k < nsteps; k++) {
        int kk = kbase + k;
        unsigned a[2][4];
        int colb = kk * 16 + (lane >> 4) * 8;
        #pragma unroll
        for (int mt = 0; mt < 2; mt++) {
            int row = wm + mt * 16 + (lane & 7) + ((lane >> 3) & 1) * 8;
            unsigned ad = sbase + (unsigned)((row * STRD + colb) * 2);
            asm volatile("ldmatrix.sync.aligned.m8n8.x4.shared.b16 {%0,%1,%2,%3}, [%4];"
                : "=r"(a[mt][0]), "=r"(a[mt][1]), "=r"(a[mt][2]), "=r"(a[mt][3])
                : "r"(ad));
        }
        uint4 b01 = wp[(kk * 4 + (wn >> 4)) * 32 + lane];
        uint4 b23 = wp[(kk * 4 + (wn >> 4) + 1) * 32 + lane];
        #pragma unroll
        for (int mt = 0; mt < 2; mt++) {
            mma16816(acc[mt][0], a[mt], b01.x, b01.y);
            mma16816(acc[mt][1], a[mt], b01.z, b01.w);
            mma16816(acc[mt][2], a[mt], b23.x, b23.y);
            mma16816(acc[mt][3], a[mt], b23.z, b23.w);
        }
    }
}

__device__ __forceinline__ void store_gates(float acc[2][4][4], float* abuf,
                                            int wm, int wn, int lane) {
    #pragma unroll
    for (int mt = 0; mt < 2; mt++)
        #pragma unroll
        for (int nt = 0; nt < 4; nt++) {
            int r  = wm + mt * 16 + (lane >> 2);
            int cc = wn + nt * 8 + (lane & 3) * 2;
            abuf[r * 68 + cc]           = acc[mt][nt][0];
            abuf[r * 68 + cc + 1]       = acc[mt][nt][1];
            abuf[(r + 8) * 68 + cc]     = acc[mt][nt][2];
            abuf[(r + 8) * 68 + cc + 1] = acc[mt][nt][3];
        }
}

// Poll the group's 16 per-CTA flags until all >= target (R5-proven ordering pattern).
__device__ __forceinline__ void wait_flags(volatile unsigned* f, unsigned target,
                                           int wg_tid, int barid) {
    if (wg_tid < GSIZE) {
        while (f[wg_tid] < target) __nanosleep(32);
    }
    __threadfence();
    if (barid == 1) { BAR_SYNC(1, 128); } else { BAR_SYNC(2, 128); }
}

// ---------------- kernels ----------------
__global__ void reset_kernel(const float* __restrict__ x) {
    int idx = blockIdx.x * blockDim.x + threadIdx.x;   // 131072
    g_h1[0][idx] = __float2half(0.0f);
    g_h2[0][idx] = __float2half(0.0f);
    int t = idx >> 9, b = idx & 511;
    g_xT[idx] = x[b * Tt + t];
    if (idx < 128) { g_f1[idx] = 0u; g_f2[idx] = 0u; }
}

__global__ void __launch_bounds__(256, 1)
lstm_main(const float* __restrict__ w_ih0, const float* __restrict__ w_hh0,
          const float* __restrict__ b_ih0, const float* __restrict__ b_hh0,
          const float* __restrict__ w_ih1, const float* __restrict__ w_hh1,
          const float* __restrict__ b_ih1, const float* __restrict__ b_hh1)
{
    extern __shared__ char smem[];
    const uint4* wp0  = (const uint4*)(smem + OFF_WP0);
    const uint4* wp1h = (const uint4*)(smem + OFF_WP1H);
    const uint4* wp1x = (const uint4*)(smem + OFF_WP1X);
    const __half* tH1 = (const __half*)(smem + OFF_H1A);
    const __half* tH2 = (const __half*)(smem + OFF_H2);
    float* abufA = (float*)(smem + OFF_ABUFA);
    float* abufB = (float*)(smem + OFF_ABUFB);
    float* bias0 = (float*)(smem + OFF_BIAS0);
    float* wih0c = (float*)(smem + OFF_WIH0);
    float* bias1 = (float*)(smem + OFF_BIAS1);

    const int tid    = threadIdx.x;
    const int wg_tid = tid & 127;
    const int lane   = tid & 31;
    const int warp   = tid >> 5;
    const int bg     = blockIdx.x >> 4;
    const int hs     = blockIdx.x & 15;
    const int brow0  = bg * 64;
    const int cta    = blockIdx.x;

    pack_weights((unsigned*)(smem + OFF_WP0),  w_hh0, hs);
    pack_weights((unsigned*)(smem + OFF_WP1H), w_hh1, hs);
    pack_weights((unsigned*)(smem + OFF_WP1X), w_ih1, hs);
    if (tid < 64) {
        int n = tid, gt = n >> 4, hloc = n & 15;
        int grow = gt * 256 + hs * 16 + hloc;
        bias0[n] = b_ih0[grow] + b_hh0[grow];
        wih0c[n] = w_ih0[grow];
        bias1[n] = b_ih1[grow] + b_hh1[grow];
    }
    __syncthreads();

    volatile unsigned* f1g = g_f1 + bg * GSIZE;
    volatile unsigned* f2g = g_f2 + bg * GSIZE;
    const int b   = wg_tid >> 1;           // batch row in tile (0..63)
    const int hh0 = (wg_tid & 1) * 8;      // h-subrange within 16-slice

    if (warp < 4) {
        // ================= WG0: layer-0 pipeline =================
        const int wm = (warp & 1) * 32, wn = ((warp >> 1) & 1) * 32;
        float c0[8];
        #pragma unroll
        for (int j = 0; j < 8; j++) c0[j] = 0.0f;

        // prologue: stage h1(0) (zeros)
        stage_tile128(smem + OFF_H1A, (const __half*)g_h1[0] + brow0 * 256, wg_tid);
        CP_COMMIT(); CP_WAIT0();
        BAR_SYNC(1, 128);

        #pragma unroll 1
        for (int t = 0; t < Tt; t++) {
            float xv = g_xT[t * Bsz + brow0 + b];

            float acc[2][4][4];
            #pragma unroll
            for (int mt = 0; mt < 2; mt++)
                #pragma unroll
                for (int nt = 0; nt < 4; nt++)
                    #pragma unroll
                    for (int q = 0; q < 4; q++) acc[mt][nt][q] = 0.0f;
            gemm_ksteps(acc, tH1, wp0, 0, 16, wm, wn, lane);
            store_gates(acc, abufA, wm, wn, lane);
            BAR_SYNC(1, 128);

            __half hv[8];
            #pragma unroll
            for (int j = 0; j < 8; j++) {
                int h = hh0 + j;
                float gi = abufA[b * 68 + h]      + xv * wih0c[h]      + bias0[h];
                float gf = abufA[b * 68 + 16 + h] + xv * wih0c[16 + h] + bias0[16 + h];
                float gg = abufA[b * 68 + 32 + h] + xv * wih0c[32 + h] + bias0[32 + h];
                float go = abufA[b * 68 + 48 + h] + xv * wih0c[48 + h] + bias0[48 + h];
                float iv = sigm(gi), fv = sigm(gf), gv = tanh_a(gg), ov = sigm(go);
                c0[j] = fv * c0[j] + iv * gv;
                hv[j] = __float2half(ov * tanh_a(c0[j]));
            }
            *(uint4*)(&g_h1[(t + 1) & 1][(brow0 + b) * 256 + hs * 16 + hh0])
                = *(uint4*)hv;

            __threadfence();
            BAR_SYNC(1, 128);
            if (wg_tid == 0) atomicExch(&g_f1[cta], (unsigned)(t + 1));

            wait_flags(f1g, (unsigned)(t + 1), wg_tid, 1);   // all group h1(t+1) ready
            BAR_SYNC(3, 256);     // WG1 finished reading h1(t) from stgH1A
            stage_tile128(smem + OFF_H1A,
                          (const __half*)g_h1[(t + 1) & 1] + brow0 * 256, wg_tid);
            CP_COMMIT(); CP_WAIT0();
            BAR_SYNC(1, 128);
            BAR_ARRIVE(4, 256);   // publish: stgH1A = h1(t+1)
        }
    } else {
        // ================= WG1: layer-1 pipeline =================
        const int w = warp - 4;
        const int wm = (w & 1) * 32, wn = ((w >> 1) & 1) * 32;
        float c1[8];
        #pragma unroll
        for (int j = 0; j < 8; j++) c1[j] = 0.0f;

        BAR_ARRIVE(3, 256);       // priming: allow WG0's first restage

        #pragma unroll 1
        for (int t = 0; t < Tt; t++) {
            wait_flags(f2g, (unsigned)t, wg_tid, 2);          // all group h2(t) ready
            stage_tile128(smem + OFF_H2, (const __half*)g_h2[t & 1] + brow0 * 256,
                          wg_tid);
            CP_COMMIT(); CP_WAIT0();
            BAR_SYNC(2, 128);

            float acc[2][4][4];
            #pragma unroll
            for (int mt = 0; mt < 2; mt++)
                #pragma unroll
                for (int nt = 0; nt < 4; nt++)
                    #pragma unroll
                    for (int q = 0; q < 4; q++) acc[mt][nt][q] = 0.0f;
            gemm_ksteps(acc, tH2, wp1h, 0, 16, wm, wn, lane);

            BAR_SYNC(4, 256);     // stgH1A = h1(t+1) ready (from WG0)
            gemm_ksteps(acc, tH1, wp1x, 0, 16, wm, wn, lane);
            store_gates(acc, abufB, wm, wn, lane);
            BAR_SYNC(2, 128);
            BAR_ARRIVE(3, 256);   // done reading stgH1A; WG0 may restage

            __half hv[8];
            #pragma unroll
            for (int j = 0; j < 8; j++) {
                int h = hh0 + j;
                float gi = abufB[b * 68 + h]      + bias1[h];
                float gf = abufB[b * 68 + 16 + h] + bias1[16 + h];
                float gg = abufB[b * 68 + 32 + h] + bias1[32 + h];
                float go = abufB[b * 68 + 48 + h] + bias1[48 + h];
                float iv = sigm(gi), fv = sigm(gf), gv = tanh_a(gg), ov = sigm(go);
                c1[j] = fv * c1[j] + iv * gv;
                hv[j] = __float2half(ov * tanh_a(c1[j]));
            }
            *(uint4*)(&g_h2[(t + 1) & 1][(brow0 + b) * 256 + hs * 16 + hh0])
                = *(uint4*)hv;

            __threadfence();
            BAR_SYNC(2, 128);
            if (wg_tid == 0) atomicExch(&g_f2[cta], (unsigned)(t + 1));
        }
    }
}

__global__ void epilogue_kernel(const float* __restrict__ w_lin,
                                const float* __restrict__ b_lin,
                                float* __restrict__ out) {
    int b = blockIdx.x;
    int lane = threadIdx.x;            // 32 threads
    float hv[8];
    #pragma unroll
    for (int j = 0; j < 8; j++)
        hv[j] = __half2float(g_h2[0][b * Hh + lane + j * 32]);   // (255+1)&1 = 0
    for (int p = 0; p < Pp; p++) {
        float s = 0.0f;
        #pragma unroll
        for (int j = 0; j < 8; j++)
            s += hv[j] * w_lin[p * Hh + lane + j * 32];
        #pragma unroll
        for (int off = 16; off > 0; off >>= 1)
            s += __shfl_xor_sync(0xFFFFFFFFu, s, off);
        if (lane == 0) out[b * Pp + p] = s + b_lin[p];
    }
}

// ---------------- launch ----------------
extern "C" void kernel_launch(void* const* d_in, const int* in_sizes, int n_in,
                              void* d_out, int out_size) {
    const float* x     = (const float*)d_in[0];
    const float* w_ih0 = (const float*)d_in[1];
    const float* w_hh0 = (const float*)d_in[2];
    const float* b_ih0 = (const float*)d_in[3];
    const float* b_hh0 = (const float*)d_in[4];
    const float* w_ih1 = (const float*)d_in[5];
    const float* w_hh1 = (const float*)d_in[6];
    const float* b_ih1 = (const float*)d_in[7];
    const float* b_hh1 = (const float*)d_in[8];
    const float* w_lin = (const float*)d_in[9];
    const float* b_lin = (const float*)d_in[10];

    cudaFuncSetAttribute(lstm_main, cudaFuncAttributeMaxDynamicSharedMemorySize,
                         SMEM_BYTES);

    reset_kernel<<<512, 256>>>(x);
    lstm_main<<<128, 256, SMEM_BYTES>>>(w_ih0, w_hh0, b_ih0, b_hh0,
                                        w_ih1, w_hh1, b_ih1, b_hh1);
    epilogue_kernel<<<Bsz, 32>>>(w_lin, b_lin, (float*)d_out);
}